// round 14
// baseline (speedup 1.0000x reference)
#include <cuda_runtime.h>
#include <cuda_bf16.h>
#include <cstdint>
#include <stdint.h>
#include <math.h>

// Problem constants
#define Dd 1024   // feature dim
#define Cc 1000   // prototypes
#define Bb 128    // batch
#define RT 1128   // Cc + Bb stacked rows
#define MP 1152   // RT padded to multiple of 64
#define PREPROWS (MP / 4)   // 288 row-blocks (4 rows each)

// Scratch (device globals — no allocation allowed)
__device__ __nv_bfloat16 g_Abf[MP * Dd];   // [mu; x; 0] bf16
__device__ __nv_bfloat16 g_Bbf[Dd * Dd];   // tril(L)^T bf16 [n][k]
__device__ __nv_bfloat16 g_MAbf[MP * Dd];  // MA = [mu;x] @ tril(L)
__device__ float g_q[MP];                  // ||MA_r||^2 + 1e-6||in_r||^2
__device__ float g_bd[RT];                 // beta . in_r

// ---------------------------------------------------------------------------
// helpers
// ---------------------------------------------------------------------------
__device__ __forceinline__ void ldsm_x4(uint32_t* r, uint32_t addr) {
    asm volatile("ldmatrix.sync.aligned.m8n8.x4.shared.b16 {%0,%1,%2,%3}, [%4];\n"
                 : "=r"(r[0]), "=r"(r[1]), "=r"(r[2]), "=r"(r[3]) : "r"(addr));
}

__device__ __forceinline__ void mma_bf16(float* d, const uint32_t* a,
                                         uint32_t b0, uint32_t b1) {
    asm volatile(
        "mma.sync.aligned.m16n8k16.row.col.f32.bf16.bf16.f32 "
        "{%0,%1,%2,%3}, {%4,%5,%6,%7}, {%8,%9}, {%0,%1,%2,%3};\n"
        : "+f"(d[0]), "+f"(d[1]), "+f"(d[2]), "+f"(d[3])
        : "r"(a[0]), "r"(a[1]), "r"(a[2]), "r"(a[3]), "r"(b0), "r"(b1));
}

// ---------------------------------------------------------------------------
// 0) prep (block-range dispatch, de-churned):
//    [0, 288):       4 rows of [mu;x;0] per block: bf16 convert + input stats
//    [288, 288+256): 64x64 tril+transpose tile of L (live iff kTile >= nTile)
// ---------------------------------------------------------------------------
__global__ __launch_bounds__(256) void prep(const float* __restrict__ x,
                                            const float* __restrict__ mu,
                                            const float* __restrict__ beta,
                                            const float* __restrict__ L) {
    int bid = blockIdx.x;
    int tid = threadIdx.x;

    if (bid < PREPROWS) {
        // ---- 4 rows per block; 64 threads/row; 4 strided float4s/thread ----
        int rid = tid >> 6;          // row within block (0..3)
        int r = bid * 4 + rid;
        int col = tid & 63;          // float4 lane within row
        const float* src = nullptr;
        if (r < Cc)      src = mu + (size_t)r * Dd;
        else if (r < RT) src = x + (size_t)(r - Cc) * Dd;

        float sin_ = 0.f, sb = 0.f;
#pragma unroll
        for (int j = 0; j < 4; j++) {
            int k = (col + 64 * j) * 4;
            float4 v = src ? *reinterpret_cast<const float4*>(src + k)
                           : make_float4(0.f, 0.f, 0.f, 0.f);
            __nv_bfloat162 p0 = __floats2bfloat162_rn(v.x, v.y);
            __nv_bfloat162 p1 = __floats2bfloat162_rn(v.z, v.w);
            uint2 o;
            o.x = *reinterpret_cast<uint32_t*>(&p0);
            o.y = *reinterpret_cast<uint32_t*>(&p1);
            *reinterpret_cast<uint2*>(g_Abf + (size_t)r * Dd + k) = o;
            if (src) {
                float4 b4 = *reinterpret_cast<const float4*>(beta + k);
                sin_ += v.x * v.x + v.y * v.y + v.z * v.z + v.w * v.w;
                sb += b4.x * v.x + b4.y * v.y + b4.z * v.z + b4.w * v.w;
            }
        }
#pragma unroll
        for (int off = 16; off > 0; off >>= 1) {
            sin_ += __shfl_xor_sync(0xFFFFFFFFu, sin_, off);
            sb += __shfl_xor_sync(0xFFFFFFFFu, sb, off);
        }
        __shared__ float red[4][2][2];
        int wir = (tid >> 5) & 1;    // warp within row (0/1)
        if ((tid & 31) == 0) { red[rid][wir][0] = sin_; red[rid][wir][1] = sb; }
        __syncthreads();
        if (col == 0) {
            if (r < RT) {
                g_q[r] = 1e-6f * (red[rid][0][0] + red[rid][1][0]);
                g_bd[r] = red[rid][0][1] + red[rid][1][1];
            } else {
                g_q[r] = 0.f;
            }
        }
    } else {
        // ---- 64x64 tril+transpose tile ----
        int tileId = bid - PREPROWS;
        int tx64 = tileId & 15;      // k tile
        int ty64 = tileId >> 4;      // n tile
        if (tx64 < ty64) return;     // g_Bbf[n][k] never read for k < 64*(n/64)
        int bx = tx64 * 64, by = ty64 * 64;
        __shared__ float t[64][65];
        int c = tid & 63;
        int rb = tid >> 6;           // 0..3
#pragma unroll
        for (int i = rb; i < 64; i += 4)
            t[i][c] = L[(size_t)(bx + i) * Dd + by + c];
        __syncthreads();
#pragma unroll
        for (int i = rb; i < 64; i += 4) {
            int n = by + i, k = bx + c;
            float v = (k >= n) ? t[c][i] : 0.f;
            g_Bbf[(size_t)n * Dd + k] = __float2bfloat16(v);
        }
    }
}

// ---------------------------------------------------------------------------
// 1) gemm_ma_mma (R7-proven register-prefetch engine, verbatim):
//    g_MAbf[m][n] = sum_k g_Abf[m][k] * g_Bbf[n][k]  (NT bf16 HMMA)
//    BM=BN=64, BK=32, 128 thr, 2x2 warps, warp tile 32x32, triangular K-skip.
// ---------------------------------------------------------------------------
__global__ __launch_bounds__(128) void gemm_ma_mma() {
    __shared__ __align__(16) __nv_bfloat16 As[64][40];
    __shared__ __align__(16) __nv_bfloat16 Bs[64][40];
    int bm = blockIdx.x * 64;
    int bn = blockIdx.y * 64;
    int tid = threadIdx.x;
    int lane = tid & 31, w = tid >> 5;
    int wm = (w & 1) * 32, wn = (w >> 1) * 32;

    int lr = tid >> 1;
    int lk = (tid & 1) * 16;
    const __nv_bfloat16* aptr = g_Abf + (size_t)(bm + lr) * Dd + lk;
    const __nv_bfloat16* bptr = g_Bbf + (size_t)(bn + lr) * Dd + lk;

    float acc[2][4][4];
#pragma unroll
    for (int mt = 0; mt < 2; mt++)
#pragma unroll
        for (int nt = 0; nt < 4; nt++)
#pragma unroll
            for (int e = 0; e < 4; e++) acc[mt][nt][e] = 0.f;

    uint32_t aA[2], bA[2];
#pragma unroll
    for (int t2 = 0; t2 < 2; t2++) {
        aA[t2] = (uint32_t)__cvta_generic_to_shared(
            &As[wm + t2 * 16 + (lane & 15)][(lane >> 4) * 8]);
        bA[t2] = (uint32_t)__cvta_generic_to_shared(
            &Bs[wn + t2 * 16 + (lane & 15)][(lane >> 4) * 8]);
    }

    int kstart = bn;  // tril skip
    uint4 pa0 = *reinterpret_cast<const uint4*>(aptr + kstart);
    uint4 pa1 = *reinterpret_cast<const uint4*>(aptr + kstart + 8);
    uint4 pb0 = *reinterpret_cast<const uint4*>(bptr + kstart);
    uint4 pb1 = *reinterpret_cast<const uint4*>(bptr + kstart + 8);

    for (int k0 = kstart; k0 < Dd; k0 += 32) {
        *reinterpret_cast<uint4*>(&As[lr][lk]) = pa0;
        *reinterpret_cast<uint4*>(&As[lr][lk + 8]) = pa1;
        *reinterpret_cast<uint4*>(&Bs[lr][lk]) = pb0;
        *reinterpret_cast<uint4*>(&Bs[lr][lk + 8]) = pb1;
        __syncthreads();
        if (k0 + 32 < Dd) {
            pa0 = *reinterpret_cast<const uint4*>(aptr + k0 + 32);
            pa1 = *reinterpret_cast<const uint4*>(aptr + k0 + 40);
            pb0 = *reinterpret_cast<const uint4*>(bptr + k0 + 32);
            pb1 = *reinterpret_cast<const uint4*>(bptr + k0 + 40);
        }
#pragma unroll
        for (int ks = 0; ks < 2; ks++) {
            uint32_t off = (uint32_t)(ks * 32);
            uint32_t a0[4], a1[4], br0[4], br1[4];
            ldsm_x4(a0, aA[0] + off);
            ldsm_x4(a1, aA[1] + off);
            ldsm_x4(br0, bA[0] + off);
            ldsm_x4(br1, bA[1] + off);
#pragma unroll
            for (int mt = 0; mt < 2; mt++) {
                uint32_t* a = mt ? a1 : a0;
                mma_bf16(acc[mt][0], a, br0[0], br0[2]);
                mma_bf16(acc[mt][1], a, br0[1], br0[3]);
                mma_bf16(acc[mt][2], a, br1[0], br1[2]);
                mma_bf16(acc[mt][3], a, br1[1], br1[3]);
            }
        }
        __syncthreads();
    }

    int mrow = lane >> 2;
    int ncol = (lane & 3) * 2;
#pragma unroll
    for (int mt = 0; mt < 2; mt++) {
        float s0 = 0.f, s1 = 0.f;
        int row = bm + wm + mt * 16 + mrow;
#pragma unroll
        for (int nt = 0; nt < 4; nt++) {
            int col = bn + wn + nt * 8 + ncol;
            __nv_bfloat162 lo = __floats2bfloat162_rn(acc[mt][nt][0], acc[mt][nt][1]);
            __nv_bfloat162 hi = __floats2bfloat162_rn(acc[mt][nt][2], acc[mt][nt][3]);
            *reinterpret_cast<__nv_bfloat162*>(g_MAbf + (size_t)row * Dd + col) = lo;
            *reinterpret_cast<__nv_bfloat162*>(g_MAbf + (size_t)(row + 8) * Dd + col) = hi;
            float l0 = __bfloat162float(lo.x), l1 = __bfloat162float(lo.y);
            float h0 = __bfloat162float(hi.x), h1 = __bfloat162float(hi.y);
            s0 += l0 * l0 + l1 * l1;
            s1 += h0 * h0 + h1 * h1;
        }
        s0 += __shfl_xor_sync(0xFFFFFFFFu, s0, 1);
        s0 += __shfl_xor_sync(0xFFFFFFFFu, s0, 2);
        s1 += __shfl_xor_sync(0xFFFFFFFFu, s1, 1);
        s1 += __shfl_xor_sync(0xFFFFFFFFu, s1, 2);
        if ((lane & 3) == 0) {
            atomicAdd(&g_q[row], s0);
            atomicAdd(&g_q[row + 8], s1);
        }
    }
}

// ---------------------------------------------------------------------------
// 2) dot_fused: FULL-K cross dot + final output. 32x32 tile per block,
//    grid (4,32)=128 blocks, 256 threads: 8 warps warp-split-K (16 k each per
//    128-k iteration -> serial depth 64 MMAs). Two-stage smem reduction, then
//    fused finalize epilogue. No g_part, no finalize kernel.
// ---------------------------------------------------------------------------
__global__ __launch_bounds__(256) void dot_fused(const float* __restrict__ lmbda,
                                                 const float* __restrict__ scale,
                                                 float* __restrict__ out) {
    __shared__ __align__(16) __nv_bfloat16 As[32][136];
    __shared__ __align__(16) __nv_bfloat16 Bs[32][136];
    __shared__ float red4[4][32][32];

    int bm = blockIdx.x * 32;                // b offset
    int bn = blockIdx.y * 32;                // c offset (padded to 1024)
    int tid = threadIdx.x;
    int lane = tid & 31, w = tid >> 5;       // warp = k-sixteenth owner

    // load mapping: 32 rows x 128 k, 8 threads/row, 16 elems (2 uint4) each
    int lrow = tid >> 3;                     // 0..31
    int lkq = (tid & 7) * 16;                // 0..112
    const __nv_bfloat16* aptr = g_MAbf + (size_t)(Cc + bm + lrow) * Dd + lkq;
    const __nv_bfloat16* bptr = g_MAbf + (size_t)(bn + lrow) * Dd + lkq;

    float acc[2][4][4];
#pragma unroll
    for (int mt = 0; mt < 2; mt++)
#pragma unroll
        for (int nt = 0; nt < 4; nt++)
#pragma unroll
            for (int e = 0; e < 4; e++) acc[mt][nt][e] = 0.f;

    // frag addresses: warp w reads k-cols [w*16, w*16+16)
    uint32_t aA[2], bA[2];
#pragma unroll
    for (int t2 = 0; t2 < 2; t2++) {
        aA[t2] = (uint32_t)__cvta_generic_to_shared(
            &As[t2 * 16 + (lane & 15)][w * 16 + (lane >> 4) * 8]);
        bA[t2] = (uint32_t)__cvta_generic_to_shared(
            &Bs[t2 * 16 + (lane & 15)][w * 16 + (lane >> 4) * 8]);
    }

    uint4 pa0 = *reinterpret_cast<const uint4*>(aptr);
    uint4 pa1 = *reinterpret_cast<const uint4*>(aptr + 8);
    uint4 pb0 = *reinterpret_cast<const uint4*>(bptr);
    uint4 pb1 = *reinterpret_cast<const uint4*>(bptr + 8);

#pragma unroll 1
    for (int it = 0; it < 8; ++it) {         // 8 x 128 = K 1024
        *reinterpret_cast<uint4*>(&As[lrow][lkq]) = pa0;
        *reinterpret_cast<uint4*>(&As[lrow][lkq + 8]) = pa1;
        *reinterpret_cast<uint4*>(&Bs[lrow][lkq]) = pb0;
        *reinterpret_cast<uint4*>(&Bs[lrow][lkq + 8]) = pb1;
        __syncthreads();
        if (it + 1 < 8) {
            int k = (it + 1) * 128;
            pa0 = *reinterpret_cast<const uint4*>(aptr + k);
            pa1 = *reinterpret_cast<const uint4*>(aptr + k + 8);
            pb0 = *reinterpret_cast<const uint4*>(bptr + k);
            pb1 = *reinterpret_cast<const uint4*>(bptr + k + 8);
        }
        {
            uint32_t a0[4], a1[4], br0[4], br1[4];
            ldsm_x4(a0, aA[0]);
            ldsm_x4(a1, aA[1]);
            ldsm_x4(br0, bA[0]);
            ldsm_x4(br1, bA[1]);
#pragma unroll
            for (int mt = 0; mt < 2; mt++) {
                uint32_t* a = mt ? a1 : a0;
                mma_bf16(acc[mt][0], a, br0[0], br0[2]);
                mma_bf16(acc[mt][1], a, br0[1], br0[3]);
                mma_bf16(acc[mt][2], a, br1[0], br1[2]);
                mma_bf16(acc[mt][3], a, br1[1], br1[3]);
            }
        }
        __syncthreads();
    }

    // ---- two-stage reduction of 8 warp partials ----
    int mrow = lane >> 2;
    int ncol = (lane & 3) * 2;
    if (w >= 4) {
#pragma unroll
        for (int mt = 0; mt < 2; mt++)
#pragma unroll
            for (int nt = 0; nt < 4; nt++) {
                int r0 = mt * 16 + mrow;
                int c0 = nt * 8 + ncol;
                red4[w - 4][r0][c0] = acc[mt][nt][0];
                red4[w - 4][r0][c0 + 1] = acc[mt][nt][1];
                red4[w - 4][r0 + 8][c0] = acc[mt][nt][2];
                red4[w - 4][r0 + 8][c0 + 1] = acc[mt][nt][3];
            }
    }
    __syncthreads();
    if (w < 4) {
#pragma unroll
        for (int mt = 0; mt < 2; mt++)
#pragma unroll
            for (int nt = 0; nt < 4; nt++) {
                int r0 = mt * 16 + mrow;
                int c0 = nt * 8 + ncol;
                red4[w][r0][c0] += acc[mt][nt][0];
                red4[w][r0][c0 + 1] += acc[mt][nt][1];
                red4[w][r0 + 8][c0] += acc[mt][nt][2];
                red4[w][r0 + 8][c0 + 1] += acc[mt][nt][3];
            }
    }
    __syncthreads();

    // ---- fused finalize: thread t -> row t/8, cols (t%8)*4 .. +4 ----
    {
        int r = tid >> 3;
        int cb = (tid & 7) * 4;
        int b = bm + r;
        float qb = g_q[Cc + b];
        float bdb = g_bd[Cc + b];
        float lm = *lmbda;
        float sc = *scale;
        float* orow = out + (size_t)b * Cc;
#pragma unroll
        for (int j = 0; j < 4; j++) {
            int cl = cb + j;
            int c = bn + cl;
            if (c >= Cc) break;
            float s = red4[0][r][cl] + red4[1][r][cl] + red4[2][r][cl] + red4[3][r][cl];
            float quad = qb + g_q[c] - 2.f * s;
            float bd = bdb - g_bd[c];
            orow[c] = -sc * (sqrtf(quad + 1e-6f) + lm * sqrtf(bd * bd + 1e-6f));
        }
    }
}

// ---------------------------------------------------------------------------
extern "C" void kernel_launch(void* const* d_in, const int* in_sizes, int n_in,
                              void* d_out, int out_size) {
    const float *x = nullptr, *mu = nullptr, *beta = nullptr, *L = nullptr;
    const float *lmbda = nullptr, *scale = nullptr;
    for (int i = 0; i < n_in; i++) {
        const float* p = (const float*)d_in[i];
        switch (in_sizes[i]) {
            case Bb * Dd:  x = p; break;
            case Cc * Dd:  mu = p; break;
            case Dd:       beta = p; break;
            case Dd * Dd:  L = p; break;
            case 1:        if (!lmbda) lmbda = p; else scale = p; break;
            default: break;
        }
    }

    prep<<<PREPROWS + 256, 256>>>(x, mu, beta, L);
    gemm_ma_mma<<<dim3(MP / 64, Dd / 64), 128>>>();
    dot_fused<<<dim3(Bb / 32, 32), 256>>>(lmbda, scale, (float*)d_out);
}

// round 15
// speedup vs baseline: 1.0820x; 1.0820x over previous
#include <cuda_runtime.h>
#include <cuda_bf16.h>
#include <cstdint>
#include <stdint.h>
#include <math.h>

// Problem constants
#define Dd 1024   // feature dim
#define Cc 1000   // prototypes
#define Bb 128    // batch
#define RT 1128   // Cc + Bb stacked rows
#define MP 1152   // RT padded to multiple of 64
#define KS 8      // split-K for cross-dot gemm
#define KC (Dd / KS)

// Scratch (device globals — no allocation allowed)
__device__ __nv_bfloat16 g_Abf[MP * Dd];   // [mu; x; 0] bf16
__device__ __nv_bfloat16 g_Bbf[Dd * Dd];   // tril(L)^T bf16 [n][k]
__device__ __nv_bfloat16 g_MAbf[MP * Dd];  // MA = [mu;x] @ tril(L)
__device__ float g_q[MP];                  // ||MA_r||^2 + 1e-6||in_r||^2
__device__ float g_bd[RT];                 // beta . in_r
__device__ float g_part[KS * Bb * Dd];     // per-z cross-dot slices (no atomics)

// ---------------------------------------------------------------------------
// helpers
// ---------------------------------------------------------------------------
__device__ __forceinline__ void ldsm_x4(uint32_t* r, uint32_t addr) {
    asm volatile("ldmatrix.sync.aligned.m8n8.x4.shared.b16 {%0,%1,%2,%3}, [%4];\n"
                 : "=r"(r[0]), "=r"(r[1]), "=r"(r[2]), "=r"(r[3]) : "r"(addr));
}

__device__ __forceinline__ void mma_bf16(float* d, const uint32_t* a,
                                         uint32_t b0, uint32_t b1) {
    asm volatile(
        "mma.sync.aligned.m16n8k16.row.col.f32.bf16.bf16.f32 "
        "{%0,%1,%2,%3}, {%4,%5,%6,%7}, {%8,%9}, {%0,%1,%2,%3};\n"
        : "+f"(d[0]), "+f"(d[1]), "+f"(d[2]), "+f"(d[3])
        : "r"(a[0]), "r"(a[1]), "r"(a[2]), "r"(a[3]), "r"(b0), "r"(b1));
}

// ---------------------------------------------------------------------------
// 0) prep (R13-measured-best version, 6.43us):
//    [0, MP):        bf16 convert row of [mu;x;0] + input stats (seed g_q, g_bd)
//    [MP, MP+1024):  tril+transpose 32x32 tile of L (skipping never-read tiles)
// ---------------------------------------------------------------------------
__global__ __launch_bounds__(256) void prep(const float* __restrict__ x,
                                            const float* __restrict__ mu,
                                            const float* __restrict__ beta,
                                            const float* __restrict__ L) {
    int bid = blockIdx.x;
    int tid = threadIdx.x;

    if (bid < MP) {
        int r = bid;
        int k = tid * 4;
        float4 v = make_float4(0.f, 0.f, 0.f, 0.f);
        if (r < Cc)      v = *reinterpret_cast<const float4*>(mu + (size_t)r * Dd + k);
        else if (r < RT) v = *reinterpret_cast<const float4*>(x + (size_t)(r - Cc) * Dd + k);
        __nv_bfloat162 p0 = __floats2bfloat162_rn(v.x, v.y);
        __nv_bfloat162 p1 = __floats2bfloat162_rn(v.z, v.w);
        uint2 o;
        o.x = *reinterpret_cast<uint32_t*>(&p0);
        o.y = *reinterpret_cast<uint32_t*>(&p1);
        *reinterpret_cast<uint2*>(g_Abf + (size_t)r * Dd + k) = o;

        if (r >= RT) {
            if (tid == 0) g_q[r] = 0.f;
            return;
        }

        float4 b4 = *reinterpret_cast<const float4*>(beta + k);
        float sin_ = v.x * v.x + v.y * v.y + v.z * v.z + v.w * v.w;
        float sb = b4.x * v.x + b4.y * v.y + b4.z * v.z + b4.w * v.w;
#pragma unroll
        for (int off = 16; off > 0; off >>= 1) {
            sin_ += __shfl_xor_sync(0xFFFFFFFFu, sin_, off);
            sb += __shfl_xor_sync(0xFFFFFFFFu, sb, off);
        }
        __shared__ float red[2][8];
        int wid = tid >> 5, lane = tid & 31;
        if (lane == 0) { red[0][wid] = sin_; red[1][wid] = sb; }
        __syncthreads();
        if (tid == 0) {
            float t0 = 0.f, t1 = 0.f;
#pragma unroll
            for (int wq = 0; wq < 8; wq++) { t0 += red[0][wq]; t1 += red[1][wq]; }
            g_q[r] = 1e-6f * t0;   // seed; gemm epilogue atomically adds ||MA||^2
            g_bd[r] = t1;
        }
    } else {
        int tileId = bid - MP;
        int bx = (tileId & 31) * 32;   // k base
        int by = (tileId >> 5) * 32;   // n base
        // gemm reads g_Bbf[n][k] only for k >= 64*floor(n/64): skip dead tiles
        if (bx < ((by >> 6) << 6)) return;
        __shared__ float t[32][33];
        int tx = tid & 31, ty = tid >> 5;  // 32 x 8
#pragma unroll
        for (int i = ty; i < 32; i += 8)
            t[i][tx] = L[(size_t)(bx + i) * Dd + by + tx];
        __syncthreads();
#pragma unroll
        for (int i = ty; i < 32; i += 8) {
            int n = by + i, k = bx + tx;
            float v = (k >= n) ? t[tx][i] : 0.f;
            g_Bbf[(size_t)n * Dd + k] = __float2bfloat16(v);
        }
    }
}

// ---------------------------------------------------------------------------
// 1) gemm_ma_mma (R7-proven register-prefetch engine). PDL: setup runs before
//    cudaGridDependencySynchronize(); dependent loads after.
// ---------------------------------------------------------------------------
__global__ __launch_bounds__(128) void gemm_ma_mma() {
    __shared__ __align__(16) __nv_bfloat16 As[64][40];
    __shared__ __align__(16) __nv_bfloat16 Bs[64][40];
    int bm = blockIdx.x * 64;
    int bn = blockIdx.y * 64;
    int tid = threadIdx.x;
    int lane = tid & 31, w = tid >> 5;
    int wm = (w & 1) * 32, wn = (w >> 1) * 32;

    int lr = tid >> 1;
    int lk = (tid & 1) * 16;
    const __nv_bfloat16* aptr = g_Abf + (size_t)(bm + lr) * Dd + lk;
    const __nv_bfloat16* bptr = g_Bbf + (size_t)(bn + lr) * Dd + lk;

    float acc[2][4][4];
#pragma unroll
    for (int mt = 0; mt < 2; mt++)
#pragma unroll
        for (int nt = 0; nt < 4; nt++)
#pragma unroll
            for (int e = 0; e < 4; e++) acc[mt][nt][e] = 0.f;

    uint32_t aA[2], bA[2];
#pragma unroll
    for (int t2 = 0; t2 < 2; t2++) {
        aA[t2] = (uint32_t)__cvta_generic_to_shared(
            &As[wm + t2 * 16 + (lane & 15)][(lane >> 4) * 8]);
        bA[t2] = (uint32_t)__cvta_generic_to_shared(
            &Bs[wn + t2 * 16 + (lane & 15)][(lane >> 4) * 8]);
    }
    int kstart = bn;  // tril skip

    cudaGridDependencySynchronize();   // wait for prep outputs

    uint4 pa0 = *reinterpret_cast<const uint4*>(aptr + kstart);
    uint4 pa1 = *reinterpret_cast<const uint4*>(aptr + kstart + 8);
    uint4 pb0 = *reinterpret_cast<const uint4*>(bptr + kstart);
    uint4 pb1 = *reinterpret_cast<const uint4*>(bptr + kstart + 8);

    for (int k0 = kstart; k0 < Dd; k0 += 32) {
        *reinterpret_cast<uint4*>(&As[lr][lk]) = pa0;
        *reinterpret_cast<uint4*>(&As[lr][lk + 8]) = pa1;
        *reinterpret_cast<uint4*>(&Bs[lr][lk]) = pb0;
        *reinterpret_cast<uint4*>(&Bs[lr][lk + 8]) = pb1;
        __syncthreads();
        if (k0 + 32 < Dd) {
            pa0 = *reinterpret_cast<const uint4*>(aptr + k0 + 32);
            pa1 = *reinterpret_cast<const uint4*>(aptr + k0 + 40);
            pb0 = *reinterpret_cast<const uint4*>(bptr + k0 + 32);
            pb1 = *reinterpret_cast<const uint4*>(bptr + k0 + 40);
        }
#pragma unroll
        for (int ks = 0; ks < 2; ks++) {
            uint32_t off = (uint32_t)(ks * 32);
            uint32_t a0[4], a1[4], br0[4], br1[4];
            ldsm_x4(a0, aA[0] + off);
            ldsm_x4(a1, aA[1] + off);
            ldsm_x4(br0, bA[0] + off);
            ldsm_x4(br1, bA[1] + off);
#pragma unroll
            for (int mt = 0; mt < 2; mt++) {
                uint32_t* a = mt ? a1 : a0;
                mma_bf16(acc[mt][0], a, br0[0], br0[2]);
                mma_bf16(acc[mt][1], a, br0[1], br0[3]);
                mma_bf16(acc[mt][2], a, br1[0], br1[2]);
                mma_bf16(acc[mt][3], a, br1[1], br1[3]);
            }
        }
        __syncthreads();
    }

    int mrow = lane >> 2;
    int ncol = (lane & 3) * 2;
#pragma unroll
    for (int mt = 0; mt < 2; mt++) {
        float s0 = 0.f, s1 = 0.f;
        int row = bm + wm + mt * 16 + mrow;
#pragma unroll
        for (int nt = 0; nt < 4; nt++) {
            int col = bn + wn + nt * 8 + ncol;
            __nv_bfloat162 lo = __floats2bfloat162_rn(acc[mt][nt][0], acc[mt][nt][1]);
            __nv_bfloat162 hi = __floats2bfloat162_rn(acc[mt][nt][2], acc[mt][nt][3]);
            *reinterpret_cast<__nv_bfloat162*>(g_MAbf + (size_t)row * Dd + col) = lo;
            *reinterpret_cast<__nv_bfloat162*>(g_MAbf + (size_t)(row + 8) * Dd + col) = hi;
            float l0 = __bfloat162float(lo.x), l1 = __bfloat162float(lo.y);
            float h0 = __bfloat162float(hi.x), h1 = __bfloat162float(hi.y);
            s0 += l0 * l0 + l1 * l1;
            s1 += h0 * h0 + h1 * h1;
        }
        s0 += __shfl_xor_sync(0xFFFFFFFFu, s0, 1);
        s0 += __shfl_xor_sync(0xFFFFFFFFu, s0, 2);
        s1 += __shfl_xor_sync(0xFFFFFFFFu, s1, 1);
        s1 += __shfl_xor_sync(0xFFFFFFFFu, s1, 2);
        if ((lane & 3) == 0) {
            atomicAdd(&g_q[row], s0);
            atomicAdd(&g_q[row + 8], s1);
        }
    }
}

// ---------------------------------------------------------------------------
// 2) dot_mma: R7-style register-prefetch engine, per-z direct stores.
//    PDL: setup pre-sync, dependent loads post-sync.
// ---------------------------------------------------------------------------
__global__ __launch_bounds__(128) void dot_mma() {
    __shared__ __align__(16) __nv_bfloat16 As[64][40];
    __shared__ __align__(16) __nv_bfloat16 Bs[64][40];
    int bm = blockIdx.x * 64;                // b offset
    int bn = blockIdx.y * 64;                // c offset
    int kb = blockIdx.z * KC;                // k chunk base
    int tid = threadIdx.x;
    int lane = tid & 31, w = tid >> 5;
    int wm = (w & 1) * 32, wn = (w >> 1) * 32;

    int lr = tid >> 1;
    int lk = (tid & 1) * 16;
    const __nv_bfloat16* aptr = g_MAbf + (size_t)(Cc + bm + lr) * Dd + kb + lk;
    const __nv_bfloat16* bptr = g_MAbf + (size_t)(bn + lr) * Dd + kb + lk;

    float acc[2][4][4];
#pragma unroll
    for (int mt = 0; mt < 2; mt++)
#pragma unroll
        for (int nt = 0; nt < 4; nt++)
#pragma unroll
            for (int e = 0; e < 4; e++) acc[mt][nt][e] = 0.f;

    uint32_t aA[2], bA[2];
#pragma unroll
    for (int t2 = 0; t2 < 2; t2++) {
        aA[t2] = (uint32_t)__cvta_generic_to_shared(
            &As[wm + t2 * 16 + (lane & 15)][(lane >> 4) * 8]);
        bA[t2] = (uint32_t)__cvta_generic_to_shared(
            &Bs[wn + t2 * 16 + (lane & 15)][(lane >> 4) * 8]);
    }

    cudaGridDependencySynchronize();   // wait for gemm_ma_mma outputs

    uint4 pa0 = *reinterpret_cast<const uint4*>(aptr);
    uint4 pa1 = *reinterpret_cast<const uint4*>(aptr + 8);
    uint4 pb0 = *reinterpret_cast<const uint4*>(bptr);
    uint4 pb1 = *reinterpret_cast<const uint4*>(bptr + 8);

#pragma unroll 1
    for (int k0 = 0; k0 < KC; k0 += 32) {
        *reinterpret_cast<uint4*>(&As[lr][lk]) = pa0;
        *reinterpret_cast<uint4*>(&As[lr][lk + 8]) = pa1;
        *reinterpret_cast<uint4*>(&Bs[lr][lk]) = pb0;
        *reinterpret_cast<uint4*>(&Bs[lr][lk + 8]) = pb1;
        __syncthreads();
        if (k0 + 32 < KC) {
            pa0 = *reinterpret_cast<const uint4*>(aptr + k0 + 32);
            pa1 = *reinterpret_cast<const uint4*>(aptr + k0 + 40);
            pb0 = *reinterpret_cast<const uint4*>(bptr + k0 + 32);
            pb1 = *reinterpret_cast<const uint4*>(bptr + k0 + 40);
        }
#pragma unroll
        for (int ks = 0; ks < 2; ks++) {
            uint32_t off = (uint32_t)(ks * 32);
            uint32_t a0[4], a1[4], br0[4], br1[4];
            ldsm_x4(a0, aA[0] + off);
            ldsm_x4(a1, aA[1] + off);
            ldsm_x4(br0, bA[0] + off);
            ldsm_x4(br1, bA[1] + off);
#pragma unroll
            for (int mt = 0; mt < 2; mt++) {
                uint32_t* a = mt ? a1 : a0;
                mma_bf16(acc[mt][0], a, br0[0], br0[2]);
                mma_bf16(acc[mt][1], a, br0[1], br0[3]);
                mma_bf16(acc[mt][2], a, br1[0], br1[2]);
                mma_bf16(acc[mt][3], a, br1[1], br1[3]);
            }
        }
        __syncthreads();
    }

    int mrow = lane >> 2;
    int ncol = (lane & 3) * 2;
    float* outz = g_part + (size_t)blockIdx.z * Bb * Dd;
#pragma unroll
    for (int mt = 0; mt < 2; mt++)
#pragma unroll
        for (int nt = 0; nt < 4; nt++) {
            int row = bm + wm + mt * 16 + mrow;
            int col = bn + wn + nt * 8 + ncol;
            *reinterpret_cast<float2*>(outz + (size_t)row * Dd + col) =
                make_float2(acc[mt][nt][0], acc[mt][nt][1]);
            *reinterpret_cast<float2*>(outz + (size_t)(row + 8) * Dd + col) =
                make_float2(acc[mt][nt][2], acc[mt][nt][3]);
        }
}

// ---------------------------------------------------------------------------
// 3) Finalize (8-slice sum). PDL: lmbda/scale (independent inputs) + index
//    math pre-sync; dependent g_part/g_q/g_bd loads post-sync.
// ---------------------------------------------------------------------------
#define C4 (Cc / 4)   // 250
__global__ __launch_bounds__(128) void finalize(const float* __restrict__ lmbda,
                                                const float* __restrict__ scale,
                                                float* __restrict__ out) {
    int idx = blockIdx.x * 128 + threadIdx.x;
    int b = idx / C4;
    int c = (idx - b * C4) * 4;
    float lm = *lmbda;   // independent input: load pre-sync
    float sc = *scale;

    cudaGridDependencySynchronize();   // wait for dot_mma (and, transitively, gemm)

    if (idx >= Bb * C4) return;

    float4 s = make_float4(0.f, 0.f, 0.f, 0.f);
#pragma unroll
    for (int z = 0; z < KS; z++) {
        float4 p = *reinterpret_cast<const float4*>(
            g_part + ((size_t)z * Bb + b) * Dd + c);
        s.x += p.x; s.y += p.y; s.z += p.z; s.w += p.w;
    }
    float4 qc = *reinterpret_cast<const float4*>(g_q + c);
    float4 bdc = *reinterpret_cast<const float4*>(g_bd + c);
    float qb = g_q[Cc + b];
    float bdb = g_bd[Cc + b];
    float4 o;
    {
        float quad = qb + qc.x - 2.f * s.x;
        float bd = bdb - bdc.x;
        o.x = -sc * (sqrtf(quad + 1e-6f) + lm * sqrtf(bd * bd + 1e-6f));
    }
    {
        float quad = qb + qc.y - 2.f * s.y;
        float bd = bdb - bdc.y;
        o.y = -sc * (sqrtf(quad + 1e-6f) + lm * sqrtf(bd * bd + 1e-6f));
    }
    {
        float quad = qb + qc.z - 2.f * s.z;
        float bd = bdb - bdc.z;
        o.z = -sc * (sqrtf(quad + 1e-6f) + lm * sqrtf(bd * bd + 1e-6f));
    }
    {
        float quad = qb + qc.w - 2.f * s.w;
        float bd = bdb - bdc.w;
        o.w = -sc * (sqrtf(quad + 1e-6f) + lm * sqrtf(bd * bd + 1e-6f));
    }
    *reinterpret_cast<float4*>(out + (size_t)b * Cc + c) = o;
}

// ---------------------------------------------------------------------------
extern "C" void kernel_launch(void* const* d_in, const int* in_sizes, int n_in,
                              void* d_out, int out_size) {
    const float *x = nullptr, *mu = nullptr, *beta = nullptr, *L = nullptr;
    const float *lmbda = nullptr, *scale = nullptr;
    for (int i = 0; i < n_in; i++) {
        const float* p = (const float*)d_in[i];
        switch (in_sizes[i]) {
            case Bb * Dd:  x = p; break;
            case Cc * Dd:  mu = p; break;
            case Dd:       beta = p; break;
            case Dd * Dd:  L = p; break;
            case 1:        if (!lmbda) lmbda = p; else scale = p; break;
            default: break;
        }
    }

    // Kernel 0: normal launch (no PDL vs harness's prior stream work)
    prep<<<MP + 1024, 256>>>(x, mu, beta, L);

    // Kernels 1-3: PDL (programmatic stream serialization) — blocks may launch
    // during predecessor drain; each kernel GDS-waits before dependent reads.
    cudaLaunchAttribute attr[1];
    attr[0].id = cudaLaunchAttributeProgrammaticStreamSerialization;
    attr[0].val.programmaticStreamSerializationAllowed = 1;

    {
        cudaLaunchConfig_t cfg = {};
        cfg.gridDim = dim3(MP / 64, Dd / 64);
        cfg.blockDim = dim3(128);
        cfg.attrs = attr;
        cfg.numAttrs = 1;
        cudaLaunchKernelEx(&cfg, gemm_ma_mma);
    }
    {
        cudaLaunchConfig_t cfg = {};
        cfg.gridDim = dim3(Bb / 64, Dd / 64, KS);
        cfg.blockDim = dim3(128);
        cfg.attrs = attr;
        cfg.numAttrs = 1;
        cudaLaunchKernelEx(&cfg, dot_mma);
    }
    {
        cudaLaunchConfig_t cfg = {};
        cfg.gridDim = dim3((Bb * C4 + 127) / 128);
        cfg.blockDim = dim3(128);
        cfg.attrs = attr;
        cfg.numAttrs = 1;
        cudaLaunchKernelEx(&cfg, finalize, lmbda, scale, (float*)d_out);
    }
}

// round 16
// speedup vs baseline: 1.0943x; 1.0114x over previous
#include <cuda_runtime.h>
#include <cuda_bf16.h>
#include <cstdint>
#include <stdint.h>
#include <math.h>

// Problem constants
#define Dd 1024   // feature dim
#define Cc 1000   // prototypes
#define Bb 128    // batch
#define RT 1128   // Cc + Bb stacked rows
#define MP 1152   // RT padded to multiple of 64
#define KS 4      // split-K for cross-dot gemm (halved: finalize reads 2.25MB)
#define KC (Dd / KS)

// Scratch (device globals — no allocation allowed)
__device__ __nv_bfloat16 g_Abf[MP * Dd];   // [mu; x; 0] bf16
__device__ __nv_bfloat16 g_Bbf[Dd * Dd];   // tril(L)^T bf16 [n][k]
__device__ __nv_bfloat16 g_MAbf[MP * Dd];  // MA = [mu;x] @ tril(L)
__device__ float g_q[MP];                  // ||MA_r||^2 + 1e-6||in_r||^2
__device__ float g_bd[RT];                 // beta . in_r
__device__ float g_part[KS * Bb * Dd];     // per-z cross-dot slices (no atomics)

// ---------------------------------------------------------------------------
// helpers
// ---------------------------------------------------------------------------
__device__ __forceinline__ void ldsm_x4(uint32_t* r, uint32_t addr) {
    asm volatile("ldmatrix.sync.aligned.m8n8.x4.shared.b16 {%0,%1,%2,%3}, [%4];\n"
                 : "=r"(r[0]), "=r"(r[1]), "=r"(r[2]), "=r"(r[3]) : "r"(addr));
}

__device__ __forceinline__ void mma_bf16(float* d, const uint32_t* a,
                                         uint32_t b0, uint32_t b1) {
    asm volatile(
        "mma.sync.aligned.m16n8k16.row.col.f32.bf16.bf16.f32 "
        "{%0,%1,%2,%3}, {%4,%5,%6,%7}, {%8,%9}, {%0,%1,%2,%3};\n"
        : "+f"(d[0]), "+f"(d[1]), "+f"(d[2]), "+f"(d[3])
        : "r"(a[0]), "r"(a[1]), "r"(a[2]), "r"(a[3]), "r"(b0), "r"(b1));
}

// ---------------------------------------------------------------------------
// 0) prep (R13/R15-measured-best version):
//    [0, MP):        bf16 convert row of [mu;x;0] + input stats (seed g_q, g_bd)
//    [MP, MP+1024):  tril+transpose 32x32 tile of L (skipping never-read tiles)
// ---------------------------------------------------------------------------
__global__ __launch_bounds__(256) void prep(const float* __restrict__ x,
                                            const float* __restrict__ mu,
                                            const float* __restrict__ beta,
                                            const float* __restrict__ L) {
    int bid = blockIdx.x;
    int tid = threadIdx.x;

    if (bid < MP) {
        int r = bid;
        int k = tid * 4;
        float4 v = make_float4(0.f, 0.f, 0.f, 0.f);
        if (r < Cc)      v = *reinterpret_cast<const float4*>(mu + (size_t)r * Dd + k);
        else if (r < RT) v = *reinterpret_cast<const float4*>(x + (size_t)(r - Cc) * Dd + k);
        __nv_bfloat162 p0 = __floats2bfloat162_rn(v.x, v.y);
        __nv_bfloat162 p1 = __floats2bfloat162_rn(v.z, v.w);
        uint2 o;
        o.x = *reinterpret_cast<uint32_t*>(&p0);
        o.y = *reinterpret_cast<uint32_t*>(&p1);
        *reinterpret_cast<uint2*>(g_Abf + (size_t)r * Dd + k) = o;

        if (r >= RT) {
            if (tid == 0) g_q[r] = 0.f;
            return;
        }

        float4 b4 = *reinterpret_cast<const float4*>(beta + k);
        float sin_ = v.x * v.x + v.y * v.y + v.z * v.z + v.w * v.w;
        float sb = b4.x * v.x + b4.y * v.y + b4.z * v.z + b4.w * v.w;
#pragma unroll
        for (int off = 16; off > 0; off >>= 1) {
            sin_ += __shfl_xor_sync(0xFFFFFFFFu, sin_, off);
            sb += __shfl_xor_sync(0xFFFFFFFFu, sb, off);
        }
        __shared__ float red[2][8];
        int wid = tid >> 5, lane = tid & 31;
        if (lane == 0) { red[0][wid] = sin_; red[1][wid] = sb; }
        __syncthreads();
        if (tid == 0) {
            float t0 = 0.f, t1 = 0.f;
#pragma unroll
            for (int wq = 0; wq < 8; wq++) { t0 += red[0][wq]; t1 += red[1][wq]; }
            g_q[r] = 1e-6f * t0;   // seed; gemm epilogue atomically adds ||MA||^2
            g_bd[r] = t1;
        }
    } else {
        int tileId = bid - MP;
        int bx = (tileId & 31) * 32;   // k base
        int by = (tileId >> 5) * 32;   // n base
        // gemm reads g_Bbf[n][k] only for k >= 64*floor(n/64): skip dead tiles
        if (bx < ((by >> 6) << 6)) return;
        __shared__ float t[32][33];
        int tx = tid & 31, ty = tid >> 5;  // 32 x 8
#pragma unroll
        for (int i = ty; i < 32; i += 8)
            t[i][tx] = L[(size_t)(bx + i) * Dd + by + tx];
        __syncthreads();
#pragma unroll
        for (int i = ty; i < 32; i += 8) {
            int n = by + i, k = bx + tx;
            float v = (k >= n) ? t[tx][i] : 0.f;
            g_Bbf[(size_t)n * Dd + k] = __float2bfloat16(v);
        }
    }
}

// ---------------------------------------------------------------------------
// 1) gemm_ma_mma (R7-proven register-prefetch engine). PDL: setup pre-sync,
//    dependent loads post-sync.
// ---------------------------------------------------------------------------
__global__ __launch_bounds__(128) void gemm_ma_mma() {
    __shared__ __align__(16) __nv_bfloat16 As[64][40];
    __shared__ __align__(16) __nv_bfloat16 Bs[64][40];
    int bm = blockIdx.x * 64;
    int bn = blockIdx.y * 64;
    int tid = threadIdx.x;
    int lane = tid & 31, w = tid >> 5;
    int wm = (w & 1) * 32, wn = (w >> 1) * 32;

    int lr = tid >> 1;
    int lk = (tid & 1) * 16;
    const __nv_bfloat16* aptr = g_Abf + (size_t)(bm + lr) * Dd + lk;
    const __nv_bfloat16* bptr = g_Bbf + (size_t)(bn + lr) * Dd + lk;

    float acc[2][4][4];
#pragma unroll
    for (int mt = 0; mt < 2; mt++)
#pragma unroll
        for (int nt = 0; nt < 4; nt++)
#pragma unroll
            for (int e = 0; e < 4; e++) acc[mt][nt][e] = 0.f;

    uint32_t aA[2], bA[2];
#pragma unroll
    for (int t2 = 0; t2 < 2; t2++) {
        aA[t2] = (uint32_t)__cvta_generic_to_shared(
            &As[wm + t2 * 16 + (lane & 15)][(lane >> 4) * 8]);
        bA[t2] = (uint32_t)__cvta_generic_to_shared(
            &Bs[wn + t2 * 16 + (lane & 15)][(lane >> 4) * 8]);
    }
    int kstart = bn;  // tril skip

    cudaGridDependencySynchronize();   // wait for prep outputs

    uint4 pa0 = *reinterpret_cast<const uint4*>(aptr + kstart);
    uint4 pa1 = *reinterpret_cast<const uint4*>(aptr + kstart + 8);
    uint4 pb0 = *reinterpret_cast<const uint4*>(bptr + kstart);
    uint4 pb1 = *reinterpret_cast<const uint4*>(bptr + kstart + 8);

    for (int k0 = kstart; k0 < Dd; k0 += 32) {
        *reinterpret_cast<uint4*>(&As[lr][lk]) = pa0;
        *reinterpret_cast<uint4*>(&As[lr][lk + 8]) = pa1;
        *reinterpret_cast<uint4*>(&Bs[lr][lk]) = pb0;
        *reinterpret_cast<uint4*>(&Bs[lr][lk + 8]) = pb1;
        __syncthreads();
        if (k0 + 32 < Dd) {
            pa0 = *reinterpret_cast<const uint4*>(aptr + k0 + 32);
            pa1 = *reinterpret_cast<const uint4*>(aptr + k0 + 40);
            pb0 = *reinterpret_cast<const uint4*>(bptr + k0 + 32);
            pb1 = *reinterpret_cast<const uint4*>(bptr + k0 + 40);
        }
#pragma unroll
        for (int ks = 0; ks < 2; ks++) {
            uint32_t off = (uint32_t)(ks * 32);
            uint32_t a0[4], a1[4], br0[4], br1[4];
            ldsm_x4(a0, aA[0] + off);
            ldsm_x4(a1, aA[1] + off);
            ldsm_x4(br0, bA[0] + off);
            ldsm_x4(br1, bA[1] + off);
#pragma unroll
            for (int mt = 0; mt < 2; mt++) {
                uint32_t* a = mt ? a1 : a0;
                mma_bf16(acc[mt][0], a, br0[0], br0[2]);
                mma_bf16(acc[mt][1], a, br0[1], br0[3]);
                mma_bf16(acc[mt][2], a, br1[0], br1[2]);
                mma_bf16(acc[mt][3], a, br1[1], br1[3]);
            }
        }
        __syncthreads();
    }

    int mrow = lane >> 2;
    int ncol = (lane & 3) * 2;
#pragma unroll
    for (int mt = 0; mt < 2; mt++) {
        float s0 = 0.f, s1 = 0.f;
        int row = bm + wm + mt * 16 + mrow;
#pragma unroll
        for (int nt = 0; nt < 4; nt++) {
            int col = bn + wn + nt * 8 + ncol;
            __nv_bfloat162 lo = __floats2bfloat162_rn(acc[mt][nt][0], acc[mt][nt][1]);
            __nv_bfloat162 hi = __floats2bfloat162_rn(acc[mt][nt][2], acc[mt][nt][3]);
            *reinterpret_cast<__nv_bfloat162*>(g_MAbf + (size_t)row * Dd + col) = lo;
            *reinterpret_cast<__nv_bfloat162*>(g_MAbf + (size_t)(row + 8) * Dd + col) = hi;
            float l0 = __bfloat162float(lo.x), l1 = __bfloat162float(lo.y);
            float h0 = __bfloat162float(hi.x), h1 = __bfloat162float(hi.y);
            s0 += l0 * l0 + l1 * l1;
            s1 += h0 * h0 + h1 * h1;
        }
        s0 += __shfl_xor_sync(0xFFFFFFFFu, s0, 1);
        s0 += __shfl_xor_sync(0xFFFFFFFFu, s0, 2);
        s1 += __shfl_xor_sync(0xFFFFFFFFu, s1, 1);
        s1 += __shfl_xor_sync(0xFFFFFFFFu, s1, 2);
        if ((lane & 3) == 0) {
            atomicAdd(&g_q[row], s0);
            atomicAdd(&g_q[row + 8], s1);
        }
    }
}

// ---------------------------------------------------------------------------
// 2) dot_mma: R7-style register-prefetch engine, per-z direct stores.
//    KS=4: grid (2,16,4)=128 blocks, KC=256 (8 k-iterations per block).
// ---------------------------------------------------------------------------
__global__ __launch_bounds__(128) void dot_mma() {
    __shared__ __align__(16) __nv_bfloat16 As[64][40];
    __shared__ __align__(16) __nv_bfloat16 Bs[64][40];
    int bm = blockIdx.x * 64;                // b offset
    int bn = blockIdx.y * 64;                // c offset
    int kb = blockIdx.z * KC;                // k chunk base
    int tid = threadIdx.x;
    int lane = tid & 31, w = tid >> 5;
    int wm = (w & 1) * 32, wn = (w >> 1) * 32;

    int lr = tid >> 1;
    int lk = (tid & 1) * 16;
    const __nv_bfloat16* aptr = g_MAbf + (size_t)(Cc + bm + lr) * Dd + kb + lk;
    const __nv_bfloat16* bptr = g_MAbf + (size_t)(bn + lr) * Dd + kb + lk;

    float acc[2][4][4];
#pragma unroll
    for (int mt = 0; mt < 2; mt++)
#pragma unroll
        for (int nt = 0; nt < 4; nt++)
#pragma unroll
            for (int e = 0; e < 4; e++) acc[mt][nt][e] = 0.f;

    uint32_t aA[2], bA[2];
#pragma unroll
    for (int t2 = 0; t2 < 2; t2++) {
        aA[t2] = (uint32_t)__cvta_generic_to_shared(
            &As[wm + t2 * 16 + (lane & 15)][(lane >> 4) * 8]);
        bA[t2] = (uint32_t)__cvta_generic_to_shared(
            &Bs[wn + t2 * 16 + (lane & 15)][(lane >> 4) * 8]);
    }

    cudaGridDependencySynchronize();   // wait for gemm_ma_mma outputs

    uint4 pa0 = *reinterpret_cast<const uint4*>(aptr);
    uint4 pa1 = *reinterpret_cast<const uint4*>(aptr + 8);
    uint4 pb0 = *reinterpret_cast<const uint4*>(bptr);
    uint4 pb1 = *reinterpret_cast<const uint4*>(bptr + 8);

#pragma unroll 1
    for (int k0 = 0; k0 < KC; k0 += 32) {
        *reinterpret_cast<uint4*>(&As[lr][lk]) = pa0;
        *reinterpret_cast<uint4*>(&As[lr][lk + 8]) = pa1;
        *reinterpret_cast<uint4*>(&Bs[lr][lk]) = pb0;
        *reinterpret_cast<uint4*>(&Bs[lr][lk + 8]) = pb1;
        __syncthreads();
        if (k0 + 32 < KC) {
            pa0 = *reinterpret_cast<const uint4*>(aptr + k0 + 32);
            pa1 = *reinterpret_cast<const uint4*>(aptr + k0 + 40);
            pb0 = *reinterpret_cast<const uint4*>(bptr + k0 + 32);
            pb1 = *reinterpret_cast<const uint4*>(bptr + k0 + 40);
        }
#pragma unroll
        for (int ks = 0; ks < 2; ks++) {
            uint32_t off = (uint32_t)(ks * 32);
            uint32_t a0[4], a1[4], br0[4], br1[4];
            ldsm_x4(a0, aA[0] + off);
            ldsm_x4(a1, aA[1] + off);
            ldsm_x4(br0, bA[0] + off);
            ldsm_x4(br1, bA[1] + off);
#pragma unroll
            for (int mt = 0; mt < 2; mt++) {
                uint32_t* a = mt ? a1 : a0;
                mma_bf16(acc[mt][0], a, br0[0], br0[2]);
                mma_bf16(acc[mt][1], a, br0[1], br0[3]);
                mma_bf16(acc[mt][2], a, br1[0], br1[2]);
                mma_bf16(acc[mt][3], a, br1[1], br1[3]);
            }
        }
        __syncthreads();
    }

    int mrow = lane >> 2;
    int ncol = (lane & 3) * 2;
    float* outz = g_part + (size_t)blockIdx.z * Bb * Dd;
#pragma unroll
    for (int mt = 0; mt < 2; mt++)
#pragma unroll
        for (int nt = 0; nt < 4; nt++) {
            int row = bm + wm + mt * 16 + mrow;
            int col = bn + wn + nt * 8 + ncol;
            *reinterpret_cast<float2*>(outz + (size_t)row * Dd + col) =
                make_float2(acc[mt][nt][0], acc[mt][nt][1]);
            *reinterpret_cast<float2*>(outz + (size_t)(row + 8) * Dd + col) =
                make_float2(acc[mt][nt][2], acc[mt][nt][3]);
        }
}

// ---------------------------------------------------------------------------
// 3) Finalize: 4-slice sum, 2 c's per thread (float2), grid 500 x 128 for
//    deeper latency-hiding parallelism. PDL as before.
// ---------------------------------------------------------------------------
#define C2 (Cc / 2)   // 500
__global__ __launch_bounds__(128) void finalize(const float* __restrict__ lmbda,
                                                const float* __restrict__ scale,
                                                float* __restrict__ out) {
    int idx = blockIdx.x * 128 + threadIdx.x;
    int b = idx / C2;
    int c = (idx - b * C2) * 2;
    float lm = *lmbda;   // independent input: load pre-sync
    float sc = *scale;

    cudaGridDependencySynchronize();   // wait for dot_mma (and transitively gemm)

    if (idx >= Bb * C2) return;

    float2 s = make_float2(0.f, 0.f);
#pragma unroll
    for (int z = 0; z < KS; z++) {
        float2 p = *reinterpret_cast<const float2*>(
            g_part + ((size_t)z * Bb + b) * Dd + c);
        s.x += p.x; s.y += p.y;
    }
    float2 qc = *reinterpret_cast<const float2*>(g_q + c);
    float2 bdc = *reinterpret_cast<const float2*>(g_bd + c);
    float qb = g_q[Cc + b];
    float bdb = g_bd[Cc + b];
    float2 o;
    {
        float quad = qb + qc.x - 2.f * s.x;
        float bd = bdb - bdc.x;
        o.x = -sc * (sqrtf(quad + 1e-6f) + lm * sqrtf(bd * bd + 1e-6f));
    }
    {
        float quad = qb + qc.y - 2.f * s.y;
        float bd = bdb - bdc.y;
        o.y = -sc * (sqrtf(quad + 1e-6f) + lm * sqrtf(bd * bd + 1e-6f));
    }
    *reinterpret_cast<float2*>(out + (size_t)b * Cc + c) = o;
}

// ---------------------------------------------------------------------------
extern "C" void kernel_launch(void* const* d_in, const int* in_sizes, int n_in,
                              void* d_out, int out_size) {
    const float *x = nullptr, *mu = nullptr, *beta = nullptr, *L = nullptr;
    const float *lmbda = nullptr, *scale = nullptr;
    for (int i = 0; i < n_in; i++) {
        const float* p = (const float*)d_in[i];
        switch (in_sizes[i]) {
            case Bb * Dd:  x = p; break;
            case Cc * Dd:  mu = p; break;
            case Dd:       beta = p; break;
            case Dd * Dd:  L = p; break;
            case 1:        if (!lmbda) lmbda = p; else scale = p; break;
            default: break;
        }
    }

    // Kernel 0: normal launch
    prep<<<MP + 1024, 256>>>(x, mu, beta, L);

    // Kernels 1-3: PDL (programmatic stream serialization)
    cudaLaunchAttribute attr[1];
    attr[0].id = cudaLaunchAttributeProgrammaticStreamSerialization;
    attr[0].val.programmaticStreamSerializationAllowed = 1;

    {
        cudaLaunchConfig_t cfg = {};
        cfg.gridDim = dim3(MP / 64, Dd / 64);
        cfg.blockDim = dim3(128);
        cfg.attrs = attr;
        cfg.numAttrs = 1;
        cudaLaunchKernelEx(&cfg, gemm_ma_mma);
    }
    {
        cudaLaunchConfig_t cfg = {};
        cfg.gridDim = dim3(Bb / 64, Dd / 64, KS);
        cfg.blockDim = dim3(128);
        cfg.attrs = attr;
        cfg.numAttrs = 1;
        cudaLaunchKernelEx(&cfg, dot_mma);
    }
    {
        cudaLaunchConfig_t cfg = {};
        cfg.gridDim = dim3((Bb * C2 + 127) / 128);
        cfg.blockDim = dim3(128);
        cfg.attrs = attr;
        cfg.numAttrs = 1;
        cudaLaunchKernelEx(&cfg, finalize, lmbda, scale, (float*)d_out);
    }
}